// round 6
// baseline (speedup 1.0000x reference)
#include <cuda_runtime.h>

#define B_   8
#define LQ   5376
#define NQ   (B_*LQ)   // 43008

// Scratch buffers (no cudaMalloc allowed)
__device__ float g_value[(size_t)NQ * 128];   // (B,Lq,16,8)
__device__ float g_offs [(size_t)NQ * 384];   // (B,Lq,16,3,4,2)
__device__ float g_attn [(size_t)NQ * 192];   // (B,Lq,16,12) raw logits
__device__ float g_sampled[(size_t)NQ * 128]; // (B,Lq,16,8) after sampling

// Packed fp32x2 FMA (sm_100+/sm_103a; double-rate fp32, exact fp32 semantics)
__device__ __forceinline__ unsigned long long fma2(unsigned long long a,
                                                   unsigned long long b,
                                                   unsigned long long c) {
    unsigned long long d;
    asm("fma.rn.f32x2 %0, %1, %2, %3;" : "=l"(d) : "l"(a), "l"(b), "l"(c));
    return d;
}
__device__ __forceinline__ float2 unpack2(unsigned long long u) {
    float2 f;
    asm("mov.b64 {%0, %1}, %2;" : "=f"(f.x), "=f"(f.y) : "l"(u));
    return f;
}

// ---------------------------------------------------------------------------
// Kernel 1: fused projection GEMM  x[NQ,128] @ [W_val | W_off | W_attn] + bias
// x gathered on the fly from the 3 feature maps. Tile 64q x 64c, K chunk 64.
// A stored PRE-SPLATTED as float2 (v,v) so the packed-FMA inner loop needs no
// register packing: per k per thread = 3x LDS.128 + 8x fma.rn.f32x2 (16 FMA).
// ---------------------------------------------------------------------------
__global__ __launch_bounds__(256) void proj_kernel(
    const float* __restrict__ fm0, const float* __restrict__ fm1, const float* __restrict__ fm2,
    const float* __restrict__ Wv, const float* __restrict__ bv,
    const float* __restrict__ Wo, const float* __restrict__ bo,
    const float* __restrict__ Wa, const float* __restrict__ ba)
{
    __shared__ float2 As2[64][64];   // [k][r], each element = (v, v)   32 KB
    __shared__ float  Ws [64][64];   // [k][c]                          16 KB

    const int tid = threadIdx.x;
    const int qg0 = blockIdx.x * 64;
    const int n0  = blockIdx.y * 64;

    // Gather mapping: r = query within tile (lanes -> consecutive queries)
    const int r  = tid & 63;
    const int kb = tid >> 6;   // 0..3
    const int qg = qg0 + r;
    const int b  = qg / LQ;
    const int q  = qg - b * LQ;
    const float* fmp; int HW, pos;
    if (q < 4096)      { fmp = fm0; HW = 4096; pos = q; }
    else if (q < 5120) { fmp = fm1; HW = 1024; pos = q - 4096; }
    else               { fmp = fm2; HW = 256;  pos = q - 5120; }
    const float* xbase = fmp + (size_t)b * 128 * HW + pos;

    // This block's 64 columns lie entirely inside one of the three matrices
    const float* Wm; const float* bm; int wstride; int nloc0;
    if (n0 < 128)      { Wm = Wv; bm = bv; wstride = 128; nloc0 = n0; }
    else if (n0 < 512) { Wm = Wo; bm = bo; wstride = 384; nloc0 = n0 - 128; }
    else               { Wm = Wa; bm = ba; wstride = 192; nloc0 = n0 - 512; }

    const int c  = tid & 63;
    const int tx = tid & 15, ty = tid >> 4;
    const int r0 = ty * 4, c0 = tx * 4;

    // acc01[i] = (row r0+i, cols c0..c0+1), acc23[i] = cols c0+2..c0+3
    unsigned long long acc01[4] = {0ull, 0ull, 0ull, 0ull};
    unsigned long long acc23[4] = {0ull, 0ull, 0ull, 0ull};

    for (int kk = 0; kk < 128; kk += 64) {
        #pragma unroll
        for (int i = 0; i < 16; i++) {
            int k = kb + i * 4;                         // 0..63
            float v = xbase[(size_t)(kk + k) * HW];     // coalesced over r
            As2[k][r] = make_float2(v, v);              // 256B/warp STS, conflict-free
        }
        #pragma unroll
        for (int i = 0; i < 16; i++) {
            int k = kb + i * 4;
            Ws[k][c] = Wm[(size_t)(kk + k) * wstride + nloc0 + c];
        }
        __syncthreads();
        #pragma unroll
        for (int k = 0; k < 64; k++) {
            // splatted A pairs: .x = (v_r0,v_r0), .y = (v_r0+1,v_r0+1)
            ulonglong2 A01 = *(const ulonglong2*)&As2[k][r0];
            ulonglong2 A23 = *(const ulonglong2*)&As2[k][r0 + 2];
            ulonglong2 W2  = *(const ulonglong2*)&Ws[k][c0];   // (w0,w1),(w2,w3)
            acc01[0] = fma2(A01.x, W2.x, acc01[0]);
            acc23[0] = fma2(A01.x, W2.y, acc23[0]);
            acc01[1] = fma2(A01.y, W2.x, acc01[1]);
            acc23[1] = fma2(A01.y, W2.y, acc23[1]);
            acc01[2] = fma2(A23.x, W2.x, acc01[2]);
            acc23[2] = fma2(A23.x, W2.y, acc23[2]);
            acc01[3] = fma2(A23.y, W2.x, acc01[3]);
            acc23[3] = fma2(A23.y, W2.y, acc23[3]);
        }
        __syncthreads();
    }

    // Epilogue: add bias, scatter to the right scratch buffer
    #pragma unroll
    for (int i = 0; i < 4; i++) {
        size_t qg_w = (size_t)(qg0 + r0 + i);
        float2 p01 = unpack2(acc01[i]);
        float2 p23 = unpack2(acc23[i]);
        float vals[4] = {p01.x, p01.y, p23.x, p23.y};
        #pragma unroll
        for (int j = 0; j < 4; j++) {
            int n = n0 + c0 + j;
            float v = vals[j] + bm[nloc0 + c0 + j];
            if (n0 < 128)      g_value[qg_w * 128 + n]         = v;
            else if (n0 < 512) g_offs [qg_w * 384 + (n - 128)] = v;
            else               g_attn [qg_w * 192 + (n - 512)] = v;
        }
    }
}

// ---------------------------------------------------------------------------
// Kernel 2: per-query softmax + bilinear sampling.
// One block per (b,q): 128 threads = 16 heads x 8 channels.
// ---------------------------------------------------------------------------
__global__ __launch_bounds__(128) void sample_kernel()
{
    const int qg = blockIdx.x;
    const int t  = threadIdx.x;
    const int h  = t >> 3;
    const int ch = t & 7;

    const int b = qg / LQ;
    const int q = qg - b * LQ;
    int posq, Wq;
    if (q < 4096)      { posq = q;        Wq = 64; }
    else if (q < 5120) { posq = q - 4096; Wq = 32; }
    else               { posq = q - 5120; Wq = 16; }
    const float invWq = 1.f / (float)Wq;
    const float refx = ((posq % Wq) + 0.5f) * invWq;
    const float refy = ((posq / Wq) + 0.5f) * invWq;

    __shared__ float s_attn[192];
    __shared__ float s_offs[384];
    for (int i = t; i < 192; i += 128) s_attn[i] = g_attn[(size_t)qg * 192 + i];
    for (int i = t; i < 384; i += 128) s_offs[i] = g_offs[(size_t)qg * 384 + i];
    __syncthreads();

    // Softmax over the 12 (level,point) logits of this head
    float av[12];
    float m = -1e30f;
    #pragma unroll
    for (int p = 0; p < 12; p++) { av[p] = s_attn[h * 12 + p]; m = fmaxf(m, av[p]); }
    float s = 0.f;
    #pragma unroll
    for (int p = 0; p < 12; p++) { av[p] = __expf(av[p] - m); s += av[p]; }
    const float inv = 1.f / s;

    const int Ws_[3] = {64, 32, 16};
    const int st [3] = {0, 4096, 5120};

    float acc = 0.f;
    #pragma unroll
    for (int l = 0; l < 3; l++) {
        const int   Wl = Ws_[l];
        const float fW = (float)Wl;
        const float* vbase = g_value + ((size_t)(b * LQ + st[l])) * 128 + h * 8 + ch;
        #pragma unroll
        for (int p = 0; p < 4; p++) {
            float ox = s_offs[h * 24 + (l * 4 + p) * 2 + 0];
            float oy = s_offs[h * 24 + (l * 4 + p) * 2 + 1];
            float x = (refx + ox / fW) * fW - 0.5f;
            float y = (refy + oy / fW) * fW - 0.5f;
            float x0f = floorf(x), y0f = floorf(y);
            int   x0 = (int)x0f,  y0 = (int)y0f;
            float wx1 = x - x0f, wx0 = 1.f - wx1;
            float wy1 = y - y0f, wy0 = 1.f - wy1;
            float aw = av[l * 4 + p] * inv;
            #pragma unroll
            for (int dy = 0; dy < 2; dy++) {
                int yi = y0 + dy;
                if ((unsigned)yi >= (unsigned)Wl) continue;
                float wy = dy ? wy1 : wy0;
                #pragma unroll
                for (int dx = 0; dx < 2; dx++) {
                    int xi = x0 + dx;
                    if ((unsigned)xi >= (unsigned)Wl) continue;
                    float wx = dx ? wx1 : wx0;
                    acc += aw * wy * wx * vbase[(size_t)(yi * Wl + xi) * 128];
                }
            }
        }
    }
    g_sampled[(size_t)qg * 128 + t] = acc;
}

// ---------------------------------------------------------------------------
// Kernel 3: output projection  sampled[NQ,128] @ W_out[128,128] + b_out,
// packed-FMA mainloop (A pre-splatted, [r][k] layout), scattered via smem.
// ---------------------------------------------------------------------------
__global__ __launch_bounds__(256) void out_kernel(
    const float* __restrict__ Wout, const float* __restrict__ bout,
    float* __restrict__ out)
{
    __shared__ float2 As2[64][32];   // [r][k], splatted (v,v)     16 KB
    __shared__ float  Ws [32][64];   // [k][c]                      8 KB
    __shared__ float  Os [64][65];   // [r][c] (+1 pad)           ~16.6 KB

    const int tid = threadIdx.x;
    const int qg0 = blockIdx.x * 64;
    const int n0  = blockIdx.y * 64;
    const int tx = tid & 15, ty = tid >> 4;
    const int r0 = ty * 4, c0 = tx * 4;

    unsigned long long acc01[4] = {0ull, 0ull, 0ull, 0ull};
    unsigned long long acc23[4] = {0ull, 0ull, 0ull, 0ull};

    const int kl = tid & 31;        // k lane for A gather
    const int rb = tid >> 5;        // 0..7
    const int cl = tid & 63;        // c lane for W gather
    const int kb = tid >> 6;        // 0..3

    for (int kk = 0; kk < 128; kk += 32) {
        #pragma unroll
        for (int j = 0; j < 8; j++) {
            int r_ = rb + j * 8;
            float v = g_sampled[(size_t)(qg0 + r_) * 128 + kk + kl]; // 128B/warp coalesced
            As2[r_][kl] = make_float2(v, v);                          // 256B/warp STS
        }
        #pragma unroll
        for (int i = 0; i < 8; i++) {
            int k_ = kb + i * 4;
            Ws[k_][cl] = Wout[(size_t)(kk + k_) * 128 + n0 + cl];
        }
        __syncthreads();
        #pragma unroll
        for (int k = 0; k < 32; k++) {
            unsigned long long a0 = *(const unsigned long long*)&As2[r0 + 0][k];
            unsigned long long a1 = *(const unsigned long long*)&As2[r0 + 1][k];
            unsigned long long a2 = *(const unsigned long long*)&As2[r0 + 2][k];
            unsigned long long a3 = *(const unsigned long long*)&As2[r0 + 3][k];
            ulonglong2 W2 = *(const ulonglong2*)&Ws[k][c0];
            acc01[0] = fma2(a0, W2.x, acc01[0]);
            acc23[0] = fma2(a0, W2.y, acc23[0]);
            acc01[1] = fma2(a1, W2.x, acc01[1]);
            acc23[1] = fma2(a1, W2.y, acc23[1]);
            acc01[2] = fma2(a2, W2.x, acc01[2]);
            acc23[2] = fma2(a2, W2.y, acc23[2]);
            acc01[3] = fma2(a3, W2.x, acc01[3]);
            acc23[3] = fma2(a3, W2.y, acc23[3]);
        }
        __syncthreads();
    }

    #pragma unroll
    for (int i = 0; i < 4; i++) {
        float2 p01 = unpack2(acc01[i]);
        float2 p23 = unpack2(acc23[i]);
        Os[r0 + i][c0 + 0] = p01.x + bout[n0 + c0 + 0];
        Os[r0 + i][c0 + 1] = p01.y + bout[n0 + c0 + 1];
        Os[r0 + i][c0 + 2] = p23.x + bout[n0 + c0 + 2];
        Os[r0 + i][c0 + 3] = p23.y + bout[n0 + c0 + 3];
    }
    __syncthreads();

    // Coalesced scatter: consecutive threads -> consecutive queries (pos)
    for (int cc = 0; cc < 64; cc += 4) {
        int c = cc + (tid >> 6);
        int r = tid & 63;
        int qg = qg0 + r;
        int b = qg / LQ;
        int q = qg - b * LQ;
        int n = n0 + c;
        size_t addr;
        if (q < 4096)      addr = ((size_t)(b * 128 + n)) * 4096 + q;
        else if (q < 5120) addr = 4194304u + ((size_t)(b * 128 + n)) * 1024 + (q - 4096);
        else               addr = 5242880u + ((size_t)(b * 128 + n)) * 256  + (q - 5120);
        out[addr] = Os[r][c];
    }
}

extern "C" void kernel_launch(void* const* d_in, const int* in_sizes, int n_in,
                              void* d_out, int out_size)
{
    const float* fm0   = (const float*)d_in[0];
    const float* fm1   = (const float*)d_in[1];
    const float* fm2   = (const float*)d_in[2];
    const float* W_off = (const float*)d_in[3];
    const float* b_off = (const float*)d_in[4];
    const float* W_att = (const float*)d_in[5];
    const float* b_att = (const float*)d_in[6];
    const float* W_val = (const float*)d_in[7];
    const float* b_val = (const float*)d_in[8];
    const float* W_out = (const float*)d_in[9];
    const float* b_out = (const float*)d_in[10];
    float* out = (float*)d_out;

    dim3 g1(NQ / 64, 11);
    proj_kernel<<<g1, 256>>>(fm0, fm1, fm2, W_val, b_val, W_off, b_off, W_att, b_att);

    sample_kernel<<<NQ, 128>>>();

    dim3 g3(NQ / 64, 2);
    out_kernel<<<g3, 256>>>(W_out, b_out, out);
}

// round 7
// speedup vs baseline: 1.6323x; 1.6323x over previous
#include <cuda_runtime.h>

#define B_   8
#define LQ   5376
#define NQ   (B_*LQ)   // 43008

// Scratch buffers (no cudaMalloc allowed)
__device__ float g_value[(size_t)NQ * 128];   // (B,Lq,16,8)
__device__ float g_offs [(size_t)NQ * 384];   // (B,Lq,16,3,4,2)
__device__ float g_attn [(size_t)NQ * 192];   // (B,Lq,16,12) raw logits
__device__ float g_sampled[(size_t)NQ * 128]; // (B,Lq,16,8) after sampling

// ---------------------------------------------------------------------------
// Kernel 1: fused projection GEMM  x[NQ,128] @ [W_val | W_off | W_attn] + bias
// x gathered on the fly from the 3 feature maps.
// Tile 128 queries x 64 cols, K chunked by 32, 8x4 per-thread micro-tile:
// per k per thread = 3x LDS.128 + 32 FFMA (A loads are warp-broadcast).
// NOTE: 128-query tiles never straddle level/batch boundaries
// (4096, 1024, 256 are all multiples of 128).
// ---------------------------------------------------------------------------
__global__ __launch_bounds__(256) void proj_kernel(
    const float* __restrict__ fm0, const float* __restrict__ fm1, const float* __restrict__ fm2,
    const float* __restrict__ Wv, const float* __restrict__ bv,
    const float* __restrict__ Wo, const float* __restrict__ bo,
    const float* __restrict__ Wa, const float* __restrict__ ba)
{
    __shared__ float As[32][128];   // [k][r]  16 KB
    __shared__ float Ws[32][64];    // [k][c]   8 KB

    const int tid = threadIdx.x;
    const int qg0 = blockIdx.x * 128;
    const int n0  = blockIdx.y * 64;

    // ---- A gather mapping: r = query within tile ----
    const int rA  = tid & 127;       // 0..127
    const int kbA = tid >> 7;        // 0..1
    const int qg = qg0 + rA;
    const int b  = qg / LQ;
    const int q  = qg - b * LQ;
    const float* fmp; int HW, pos;
    if (q < 4096)      { fmp = fm0; HW = 4096; pos = q; }
    else if (q < 5120) { fmp = fm1; HW = 1024; pos = q - 4096; }
    else               { fmp = fm2; HW = 256;  pos = q - 5120; }
    const float* xbase = fmp + (size_t)b * 128 * HW + pos;

    // ---- W mapping: this block's 64 columns lie in exactly one matrix ----
    const float* Wm; const float* bm; int wstride; int nloc0;
    if (n0 < 128)      { Wm = Wv; bm = bv; wstride = 128; nloc0 = n0; }
    else if (n0 < 512) { Wm = Wo; bm = bo; wstride = 384; nloc0 = n0 - 128; }
    else               { Wm = Wa; bm = ba; wstride = 192; nloc0 = n0 - 512; }

    const int cW  = tid & 63;        // 0..63
    const int kbW = tid >> 6;        // 0..3

    // ---- micro-tile mapping ----
    const int tx = tid & 15, ty = tid >> 4;   // 16 x 16
    const int r0 = ty * 8, c0 = tx * 4;

    float acc[8][4];
    #pragma unroll
    for (int i = 0; i < 8; i++)
        #pragma unroll
        for (int j = 0; j < 4; j++) acc[i][j] = 0.f;

    for (int kk = 0; kk < 128; kk += 32) {
        // load A chunk: 32x128, 16 elems/thread, coalesced over r
        #pragma unroll
        for (int i = 0; i < 16; i++) {
            int k = kbA + i * 2;                      // 0..31
            As[k][rA] = xbase[(size_t)(kk + k) * HW];
        }
        // load W chunk: 32x64, 8 elems/thread, coalesced over c
        #pragma unroll
        for (int i = 0; i < 8; i++) {
            int k = kbW + i * 4;
            Ws[k][cW] = Wm[(size_t)(kk + k) * wstride + nloc0 + cW];
        }
        __syncthreads();
        #pragma unroll
        for (int k = 0; k < 32; k++) {
            float4 a0 = *(const float4*)&As[k][r0];
            float4 a1 = *(const float4*)&As[k][r0 + 4];
            float4 w  = *(const float4*)&Ws[k][c0];
            acc[0][0] += a0.x * w.x; acc[0][1] += a0.x * w.y; acc[0][2] += a0.x * w.z; acc[0][3] += a0.x * w.w;
            acc[1][0] += a0.y * w.x; acc[1][1] += a0.y * w.y; acc[1][2] += a0.y * w.z; acc[1][3] += a0.y * w.w;
            acc[2][0] += a0.z * w.x; acc[2][1] += a0.z * w.y; acc[2][2] += a0.z * w.z; acc[2][3] += a0.z * w.w;
            acc[3][0] += a0.w * w.x; acc[3][1] += a0.w * w.y; acc[3][2] += a0.w * w.z; acc[3][3] += a0.w * w.w;
            acc[4][0] += a1.x * w.x; acc[4][1] += a1.x * w.y; acc[4][2] += a1.x * w.z; acc[4][3] += a1.x * w.w;
            acc[5][0] += a1.y * w.x; acc[5][1] += a1.y * w.y; acc[5][2] += a1.y * w.z; acc[5][3] += a1.y * w.w;
            acc[6][0] += a1.z * w.x; acc[6][1] += a1.z * w.y; acc[6][2] += a1.z * w.z; acc[6][3] += a1.z * w.w;
            acc[7][0] += a1.w * w.x; acc[7][1] += a1.w * w.y; acc[7][2] += a1.w * w.z; acc[7][3] += a1.w * w.w;
        }
        __syncthreads();
    }

    // Epilogue: add bias, scatter to the right scratch buffer
    float bias[4];
    #pragma unroll
    for (int j = 0; j < 4; j++) bias[j] = bm[nloc0 + c0 + j];

    #pragma unroll
    for (int i = 0; i < 8; i++) {
        size_t qg_w = (size_t)(qg0 + r0 + i);
        #pragma unroll
        for (int j = 0; j < 4; j++) {
            int n = n0 + c0 + j;
            float v = acc[i][j] + bias[j];
            if (n0 < 128)      g_value[qg_w * 128 + n]         = v;
            else if (n0 < 512) g_offs [qg_w * 384 + (n - 128)] = v;
            else               g_attn [qg_w * 192 + (n - 512)] = v;
        }
    }
}

// ---------------------------------------------------------------------------
// Kernel 2: per-query softmax + bilinear sampling.
// 4 queries per 256-thread block; per query 64 threads = 16 heads x 4
// channel-pairs, gathers are float2 (8B).
// ---------------------------------------------------------------------------
__global__ __launch_bounds__(256) void sample_kernel()
{
    const int t   = threadIdx.x;
    const int qi  = t >> 6;          // 0..3 query slot
    const int lt  = t & 63;
    const int h   = lt >> 2;         // 0..15
    const int chp = lt & 3;          // channel pair 0..3 (2 floats each)

    const int qg = blockIdx.x * 4 + qi;
    const int b = qg / LQ;
    const int q = qg - b * LQ;
    int posq, Wq;
    if (q < 4096)      { posq = q;        Wq = 64; }
    else if (q < 5120) { posq = q - 4096; Wq = 32; }
    else               { posq = q - 5120; Wq = 16; }
    const float invWq = 1.f / (float)Wq;
    const float refx = ((posq % Wq) + 0.5f) * invWq;
    const float refy = ((posq / Wq) + 0.5f) * invWq;

    __shared__ float s_attn[4][192];
    __shared__ float s_offs[4][384];
    {
        const size_t abase = (size_t)qg * 192;
        const size_t obase = (size_t)qg * 384;
        #pragma unroll
        for (int i = 0; i < 3; i++) s_attn[qi][lt + i * 64] = g_attn[abase + lt + i * 64];
        #pragma unroll
        for (int i = 0; i < 6; i++) s_offs[qi][lt + i * 64] = g_offs[obase + lt + i * 64];
    }
    __syncthreads();

    // Softmax over the 12 (level,point) logits of this head
    float av[12];
    float m = -1e30f;
    #pragma unroll
    for (int p = 0; p < 12; p++) { av[p] = s_attn[qi][h * 12 + p]; m = fmaxf(m, av[p]); }
    float s = 0.f;
    #pragma unroll
    for (int p = 0; p < 12; p++) { av[p] = __expf(av[p] - m); s += av[p]; }
    const float inv = 1.f / s;

    const int Ws_[3] = {64, 32, 16};
    const int st [3] = {0, 4096, 5120};

    float2 acc = make_float2(0.f, 0.f);
    #pragma unroll
    for (int l = 0; l < 3; l++) {
        const int   Wl = Ws_[l];
        const float fW = (float)Wl;
        const float* vbase = g_value + ((size_t)(b * LQ + st[l])) * 128 + h * 8 + chp * 2;
        #pragma unroll
        for (int p = 0; p < 4; p++) {
            float ox = s_offs[qi][h * 24 + (l * 4 + p) * 2 + 0];
            float oy = s_offs[qi][h * 24 + (l * 4 + p) * 2 + 1];
            float x = (refx + ox / fW) * fW - 0.5f;
            float y = (refy + oy / fW) * fW - 0.5f;
            float x0f = floorf(x), y0f = floorf(y);
            int   x0 = (int)x0f,  y0 = (int)y0f;
            float wx1 = x - x0f, wx0 = 1.f - wx1;
            float wy1 = y - y0f, wy0 = 1.f - wy1;
            float aw = av[l * 4 + p] * inv;
            #pragma unroll
            for (int dy = 0; dy < 2; dy++) {
                int yi = y0 + dy;
                if ((unsigned)yi >= (unsigned)Wl) continue;
                float wy = dy ? wy1 : wy0;
                #pragma unroll
                for (int dx = 0; dx < 2; dx++) {
                    int xi = x0 + dx;
                    if ((unsigned)xi >= (unsigned)Wl) continue;
                    float wx = dx ? wx1 : wx0;
                    float w = aw * wy * wx;
                    float2 v = *(const float2*)&vbase[(size_t)(yi * Wl + xi) * 128];
                    acc.x += w * v.x;
                    acc.y += w * v.y;
                }
            }
        }
    }
    *(float2*)&g_sampled[(size_t)qg * 128 + h * 8 + chp * 2] = acc;
}

// ---------------------------------------------------------------------------
// Kernel 3: output projection  sampled[NQ,128] @ W_out[128,128] + b_out,
// scattered into (B,128,H,W) per-level layout via smem transpose.
// ---------------------------------------------------------------------------
__global__ __launch_bounds__(256) void out_kernel(
    const float* __restrict__ Wout, const float* __restrict__ bout,
    float* __restrict__ out)
{
    __shared__ float As[64][65];   // [r][k]  (+1 pad)
    __shared__ float Ws[64][64];   // [k][c]
    __shared__ float Os[64][65];   // [r][c]  (+1 pad)

    const int tid = threadIdx.x;
    const int qg0 = blockIdx.x * 64;
    const int n0  = blockIdx.y * 64;
    const int tx = tid & 15, ty = tid >> 4;
    const int r0 = ty * 4, c0 = tx * 4;

    float acc[4][4];
    #pragma unroll
    for (int i = 0; i < 4; i++)
        #pragma unroll
        for (int j = 0; j < 4; j++) acc[i][j] = 0.f;

    const int kl = tid & 63;
    const int rb = tid >> 6;

    for (int kk = 0; kk < 128; kk += 64) {
        #pragma unroll
        for (int i = 0; i < 16; i++) {
            int r_ = rb + 4 * i;
            As[r_][kl] = g_sampled[(size_t)(qg0 + r_) * 128 + kk + kl];
        }
        #pragma unroll
        for (int i = 0; i < 16; i++) {
            int k_ = rb + 4 * i;
            Ws[k_][kl] = Wout[(size_t)(kk + k_) * 128 + n0 + kl];
        }
        __syncthreads();
        #pragma unroll
        for (int k = 0; k < 64; k++) {
            float4 w = *(const float4*)&Ws[k][c0];
            float a0 = As[r0 + 0][k], a1 = As[r0 + 1][k];
            float a2 = As[r0 + 2][k], a3 = As[r0 + 3][k];
            acc[0][0] += a0 * w.x; acc[0][1] += a0 * w.y; acc[0][2] += a0 * w.z; acc[0][3] += a0 * w.w;
            acc[1][0] += a1 * w.x; acc[1][1] += a1 * w.y; acc[1][2] += a1 * w.z; acc[1][3] += a1 * w.w;
            acc[2][0] += a2 * w.x; acc[2][1] += a2 * w.y; acc[2][2] += a2 * w.z; acc[2][3] += a2 * w.w;
            acc[3][0] += a3 * w.x; acc[3][1] += a3 * w.y; acc[3][2] += a3 * w.z; acc[3][3] += a3 * w.w;
        }
        __syncthreads();
    }

    #pragma unroll
    for (int i = 0; i < 4; i++)
        #pragma unroll
        for (int j = 0; j < 4; j++)
            Os[r0 + i][c0 + j] = acc[i][j] + bout[n0 + c0 + j];
    __syncthreads();

    // Coalesced scatter: consecutive threads -> consecutive queries (pos)
    for (int cc = 0; cc < 64; cc += 4) {
        int c = cc + (tid >> 6);
        int r = tid & 63;
        int qg = qg0 + r;
        int b = qg / LQ;
        int q = qg - b * LQ;
        int n = n0 + c;
        size_t addr;
        if (q < 4096)      addr = ((size_t)(b * 128 + n)) * 4096 + q;
        else if (q < 5120) addr = 4194304u + ((size_t)(b * 128 + n)) * 1024 + (q - 4096);
        else               addr = 5242880u + ((size_t)(b * 128 + n)) * 256  + (q - 5120);
        out[addr] = Os[r][c];
    }
}

extern "C" void kernel_launch(void* const* d_in, const int* in_sizes, int n_in,
                              void* d_out, int out_size)
{
    const float* fm0   = (const float*)d_in[0];
    const float* fm1   = (const float*)d_in[1];
    const float* fm2   = (const float*)d_in[2];
    const float* W_off = (const float*)d_in[3];
    const float* b_off = (const float*)d_in[4];
    const float* W_att = (const float*)d_in[5];
    const float* b_att = (const float*)d_in[6];
    const float* W_val = (const float*)d_in[7];
    const float* b_val = (const float*)d_in[8];
    const float* W_out = (const float*)d_in[9];
    const float* b_out = (const float*)d_in[10];
    float* out = (float*)d_out;

    dim3 g1(NQ / 128, 11);
    proj_kernel<<<g1, 256>>>(fm0, fm1, fm2, W_val, b_val, W_off, b_off, W_att, b_att);

    sample_kernel<<<NQ / 4, 256>>>();

    dim3 g3(NQ / 64, 2);
    out_kernel<<<g3, 256>>>(W_out, b_out, out);
}